// round 15
// baseline (speedup 1.0000x reference)
#include <cuda_runtime.h>
#include <cuda_bf16.h>
#include <cuda_fp16.h>
#include <cstdint>

constexpr int kN = 100000;
constexpr int kE = 1600000;
constexpr int kG = 2048;
constexpr int kD = 128;
constexpr int kScanBlocks = (kN + 1023) / 1024; // 98
constexpr int kBlkE = (kE + 255) / 256;          // 6250
constexpr int kBlkH = (kN * kD / 4 + 255) / 256; // 12500
constexpr int kBlkZ = (kG * kD + 255) / 256;     // 1024

// ---------------- scratch (no allocations allowed) ----------------
__device__ __half g_h16[kN * kD];            // pre-scaled rows h, fp16
__device__ __half g_m16[kN * kD];            // gathered m, fp16
__device__ __half g_whi[3 * kD * kD];        // W fp16 hi, [K][N]
__device__ __half g_wlo[3 * kD * kD];        // W fp16 lo, [K][N]
__device__ float g_inv_src[kN];
__device__ float g_inv_dst[kN];
__device__ int   g_deg_out[kN];
__device__ int   g_deg_in[kN];
__device__ int   g_row_ptr[kN + 1];
__device__ int   g_cursor[kN];
__device__ int   g_edge_src[kE];
__device__ int   g_blk[kScanBlocks];
__device__ float g_emb[kG * kD];
__device__ int   g_gcnt[kG];
__device__ float g_x1[kG * 512];
__device__ float g_x2[kG * 256];

// ---------------- mma / ldmatrix helpers (base ISA, sm_80+) ----------------
__device__ __forceinline__ uint32_t smem_u32(const void* p) {
    uint32_t a;
    asm("{ .reg .u64 t; cvta.to.shared.u64 t, %1; cvt.u32.u64 %0, t; }" : "=r"(a) : "l"(p));
    return a;
}
__device__ __forceinline__ void ldsm_x4(uint32_t* r, uint32_t addr) {
    asm volatile("ldmatrix.sync.aligned.m8n8.x4.shared.b16 {%0,%1,%2,%3}, [%4];"
                 : "=r"(r[0]), "=r"(r[1]), "=r"(r[2]), "=r"(r[3]) : "r"(addr));
}
__device__ __forceinline__ void ldsm_x4_t(uint32_t* r, uint32_t addr) {
    asm volatile("ldmatrix.sync.aligned.m8n8.x4.trans.shared.b16 {%0,%1,%2,%3}, [%4];"
                 : "=r"(r[0]), "=r"(r[1]), "=r"(r[2]), "=r"(r[3]) : "r"(addr));
}
__device__ __forceinline__ void mma16816h(float* d, const uint32_t* a, const uint32_t* b) {
    asm volatile(
        "mma.sync.aligned.m16n8k16.row.col.f32.f16.f16.f32 "
        "{%0,%1,%2,%3}, {%4,%5,%6,%7}, {%8,%9}, {%0,%1,%2,%3};"
        : "+f"(d[0]), "+f"(d[1]), "+f"(d[2]), "+f"(d[3])
        : "r"(a[0]), "r"(a[1]), "r"(a[2]), "r"(a[3]), "r"(b[0]), "r"(b[1]));
}

// ---------------- setup kernels ----------------
__global__ void k_zero_wsplit(const float* __restrict__ W0, const float* __restrict__ W1,
                              const float* __restrict__ W2) {
    if (blockIdx.x < kBlkZ) {
        int i = blockIdx.x * 256 + threadIdx.x;
        if (i < kN) { g_deg_out[i] = 0; g_deg_in[i] = 0; }
        if (i < kG * kD) g_emb[i] = 0.f;
        if (i < kG) g_gcnt[i] = 0;
    } else {
        int b = blockIdx.x - kBlkZ;
        int layer = b >> 6;
        int i = (b & 63) * 256 + threadIdx.x;
        if (i >= kD * kD) return;
        const float* W = (layer == 0) ? W0 : (layer == 1) ? W1 : W2;
        float w = W[i];
        __half h = __float2half_rn(w);
        g_whi[layer * kD * kD + i] = h;
        g_wlo[layer * kD * kD + i] = __float2half_rn(w - __half2float(h));
    }
}

__global__ void k_degrees(const int* __restrict__ src, const int* __restrict__ dst) {
    int e = blockIdx.x * blockDim.x + threadIdx.x;
    if (e >= kE) return;
    atomicAdd(&g_deg_out[src[e]], 1);
    atomicAdd(&g_deg_in[dst[e]], 1);
}

__global__ void k_scan1() {
    __shared__ int sm[1024];
    int tid = threadIdx.x;
    int i = blockIdx.x * 1024 + tid;
    int v = (i < kN) ? g_deg_in[i] : 0;
    int x = v;
    sm[tid] = x;
    __syncthreads();
    for (int off = 1; off < 1024; off <<= 1) {
        int y = (tid >= off) ? sm[tid - off] : 0;
        __syncthreads();
        x += y;
        sm[tid] = x;
        __syncthreads();
    }
    if (i < kN) g_row_ptr[i] = x - v;
    if (tid == 1023) g_blk[blockIdx.x] = x;
}

__global__ void k_scan_add_inv(const int* __restrict__ gids) {
    __shared__ int red[256];
    int tid = threadIdx.x;
    int chunk = blockIdx.x >> 2;
    int v = (tid < chunk) ? g_blk[tid] : 0;
    red[tid] = v;
    __syncthreads();
    #pragma unroll
    for (int s = 128; s; s >>= 1) {
        if (tid < s) red[tid] += red[tid + s];
        __syncthreads();
    }
    int pref = red[0];

    int i = blockIdx.x * 256 + tid;
    if (i < kN) {
        int rp = g_row_ptr[i] + pref;
        g_row_ptr[i] = rp;
        g_cursor[i]  = rp;
        g_inv_src[i] = rsqrtf((float)max(g_deg_out[i], 1));
        g_inv_dst[i] = rsqrtf((float)max(g_deg_in[i], 1));
        atomicAdd(&g_gcnt[gids[i]], 1);
    }
    if (i == 0) g_row_ptr[kN] = kE;
}

__global__ void k_scatter_f2h(const int* __restrict__ src, const int* __restrict__ dst,
                              const float* __restrict__ feats) {
    if (blockIdx.x < kBlkE) {
        int e = blockIdx.x * 256 + threadIdx.x;
        if (e >= kE) return;
        int d = dst[e];
        int pos = atomicAdd(&g_cursor[d], 1);
        g_edge_src[pos] = src[e];
    } else {
        int i = (blockIdx.x - kBlkE) * 256 + threadIdx.x;
        if (i >= kN * kD / 4) return;
        int row = i >> 5;
        float s = g_inv_src[row];
        float4 v = reinterpret_cast<const float4*>(feats)[i];
        __half2 a = __floats2half2_rn(v.x * s, v.y * s);
        __half2 b = __floats2half2_rn(v.z * s, v.w * s);
        reinterpret_cast<__half2*>(g_h16)[2 * i + 0] = a;
        reinterpret_cast<__half2*>(g_h16)[2 * i + 1] = b;
    }
}

// ---------------- GCN aggregation: one warp per dst node -> fp16 m (R13/R8 version) ----------------
__global__ void k_gather() {
    int w = (blockIdx.x * blockDim.x + threadIdx.x) >> 5;
    int lane = threadIdx.x & 31;
    if (w >= kN) return;
    int e0 = g_row_ptr[w];
    int e1 = g_row_ptr[w + 1];
    const uint2* H2 = reinterpret_cast<const uint2*>(g_h16);
    float4 acc = make_float4(0.f, 0.f, 0.f, 0.f);
    int e = e0;
    for (; e + 7 < e1; e += 8) {
        int s0 = g_edge_src[e + 0];
        int s1 = g_edge_src[e + 1];
        int s2 = g_edge_src[e + 2];
        int s3 = g_edge_src[e + 3];
        int s4 = g_edge_src[e + 4];
        int s5 = g_edge_src[e + 5];
        int s6 = g_edge_src[e + 6];
        int s7 = g_edge_src[e + 7];
        uint2 r0 = H2[(size_t)s0 * 32 + lane];
        uint2 r1 = H2[(size_t)s1 * 32 + lane];
        uint2 r2 = H2[(size_t)s2 * 32 + lane];
        uint2 r3 = H2[(size_t)s3 * 32 + lane];
        uint2 r4 = H2[(size_t)s4 * 32 + lane];
        uint2 r5 = H2[(size_t)s5 * 32 + lane];
        uint2 r6 = H2[(size_t)s6 * 32 + lane];
        uint2 r7 = H2[(size_t)s7 * 32 + lane];
        #define ACC(r) { \
            float2 a_ = __half22float2(*reinterpret_cast<__half2*>(&(r).x)); \
            float2 b_ = __half22float2(*reinterpret_cast<__half2*>(&(r).y)); \
            acc.x += a_.x; acc.y += a_.y; acc.z += b_.x; acc.w += b_.y; }
        ACC(r0) ACC(r1) ACC(r2) ACC(r3) ACC(r4) ACC(r5) ACC(r6) ACC(r7)
    }
    for (; e < e1; ++e) {
        int s = g_edge_src[e];
        uint2 r = H2[(size_t)s * 32 + lane];
        ACC(r)
    }
    #undef ACC
    float wd = g_inv_dst[w];
    uint2 o;
    *reinterpret_cast<__half2*>(&o.x) = __floats2half2_rn(acc.x * wd, acc.y * wd);
    *reinterpret_cast<__half2*>(&o.y) = __floats2half2_rn(acc.z * wd, acc.w * wd);
    reinterpret_cast<uint2*>(g_m16)[(size_t)w * 32 + lane] = o;
}

// ---------------- mma.sync GEMM: [128,128] tile, fp16 A x (fp16 hi+lo W), fp32 acc ----------------
constexpr int kSA = 136;
constexpr int kTileB = 128 * kSA * 2;            // 34816 bytes
constexpr int kOffA   = 0;
constexpr int kOffBhi = kTileB;
constexpr int kOffBlo = 2 * kTileB;
constexpr int kMmaSmemBytes = 3 * kTileB;        // 104448 -> 2 CTAs/SM

__device__ __forceinline__ void stage_tile(char* smem, int off,
                                           const unsigned short* __restrict__ src,
                                           int row0, int rows, int tid) {
    #pragma unroll
    for (int it = 0; it < 8; ++it) {
        int chunk = tid + it * 256;
        int r = chunk >> 4;
        int c8 = (chunk & 15) << 3;
        uint4 v = make_uint4(0u, 0u, 0u, 0u);
        int gr = row0 + r;
        if (gr < rows) v = *reinterpret_cast<const uint4*>(src + (size_t)gr * 128 + c8);
        *reinterpret_cast<uint4*>(smem + off + (r * kSA + c8) * 2) = v;
    }
}

// EPI=0: write fp16 h PRE-SCALED by inv_src[row]; EPI=1: atomicAdd into g_emb
template <int EPI>
__global__ void __launch_bounds__(256, 2)
k_gemm_mma(const __half* __restrict__ Bhi, const __half* __restrict__ Blo,
           const float* __restrict__ bias, const int* __restrict__ gids, int rows) {
    extern __shared__ char smem[];
    uint32_t sb = smem_u32(smem);
    int tid = threadIdx.x;
    int lane = tid & 31;
    int wid = tid >> 5;
    int row0 = blockIdx.x * 128;

    stage_tile(smem, kOffA, reinterpret_cast<const unsigned short*>(g_m16), row0, rows, tid);
    stage_tile(smem, kOffBhi, reinterpret_cast<const unsigned short*>(Bhi), 0, 128, tid);
    stage_tile(smem, kOffBlo, reinterpret_cast<const unsigned short*>(Blo), 0, 128, tid);
    __syncthreads();

    int wm = wid & 3;
    int wn = wid >> 2;
    int base_m = wm * 32;
    int base_n = wn * 64;

    int l16 = lane & 15;
    int c8  = (lane >> 4) << 3;
    uint32_t a_base = sb + ((base_m + l16) * kSA + c8) * 2;
    uint32_t b_base = sb + (l16 * kSA + base_n + c8) * 2;

    float acc[16][4];
    #pragma unroll
    for (int t = 0; t < 16; ++t)
        #pragma unroll
        for (int j = 0; j < 4; ++j) acc[t][j] = 0.f;

    #pragma unroll
    for (int pass = 0; pass < 2; ++pass) {
        int offB = (pass == 0) ? kOffBhi : kOffBlo;
        #pragma unroll
        for (int ks = 0; ks < 8; ++ks) {
            uint32_t af[2][4];
            ldsm_x4(af[0], a_base + kOffA + 0 * 16 * kSA * 2 + ks * 32);
            ldsm_x4(af[1], a_base + kOffA + 1 * 16 * kSA * 2 + ks * 32);
            uint32_t bf[4][4];
            #pragma unroll
            for (int np = 0; np < 4; ++np)
                ldsm_x4_t(bf[np], b_base + offB + ks * 16 * kSA * 2 + np * 32);
            #pragma unroll
            for (int mt = 0; mt < 2; ++mt)
                #pragma unroll
                for (int nt = 0; nt < 8; ++nt)
                    mma16816h(acc[mt * 8 + nt], af[mt], &bf[nt >> 1][(nt & 1) * 2]);
        }
    }

    #pragma unroll
    for (int mt = 0; mt < 2; ++mt) {
        int r0 = row0 + base_m + mt * 16 + (lane >> 2);
        int r1 = r0 + 8;
        int gid0 = -1, gid1 = -1;
        float sc0 = 0.f, sc1 = 0.f;
        if (EPI == 1) {
            if (r0 < rows) gid0 = gids[r0];
            if (r1 < rows) gid1 = gids[r1];
        } else {
            if (r0 < rows) sc0 = g_inv_src[r0];
            if (r1 < rows) sc1 = g_inv_src[r1];
        }
        #pragma unroll
        for (int nt = 0; nt < 8; ++nt) {
            const float* a = acc[mt * 8 + nt];
            int col = base_n + nt * 8 + ((lane & 3) << 1);
            float2 bb = *reinterpret_cast<const float2*>(&bias[col]);
            float o0x = fmaxf(a[0] + bb.x, 0.f);
            float o0y = fmaxf(a[1] + bb.y, 0.f);
            float o1x = fmaxf(a[2] + bb.x, 0.f);
            float o1y = fmaxf(a[3] + bb.y, 0.f);
            if (EPI == 0) {
                if (r0 < rows)
                    *reinterpret_cast<__half2*>(g_h16 + (size_t)r0 * 128 + col) =
                        __floats2half2_rn(o0x * sc0, o0y * sc0);
                if (r1 < rows)
                    *reinterpret_cast<__half2*>(g_h16 + (size_t)r1 * 128 + col) =
                        __floats2half2_rn(o1x * sc1, o1y * sc1);
            } else {
                if (gid0 >= 0) {
                    atomicAdd(g_emb + (size_t)gid0 * 128 + col,     o0x);
                    atomicAdd(g_emb + (size_t)gid0 * 128 + col + 1, o0y);
                }
                if (gid1 >= 0) {
                    atomicAdd(g_emb + (size_t)gid1 * 128 + col,     o1x);
                    atomicAdd(g_emb + (size_t)gid1 * 128 + col + 1, o1y);
                }
            }
        }
    }
}

// ---------------- MLP head: 16 graphs per thread (halved W re-read traffic) ----------------
template <bool NORM>
__global__ void k_mlp(const float* __restrict__ X, const float* __restrict__ W,
                      const float* __restrict__ b, float* __restrict__ Y,
                      int K, int M) {
    int idx = blockIdx.x * blockDim.x + threadIdx.x;
    int c = idx % M;
    int g0 = (idx / M) * 16;
    if (g0 >= kG) return;
    float acc[16];
    #pragma unroll
    for (int j = 0; j < 16; ++j) acc[j] = 0.f;
    for (int k = 0; k < K; ++k) {
        float w = W[(size_t)k * M + c];
        #pragma unroll
        for (int j = 0; j < 16; ++j)
            acc[j] += X[(size_t)(g0 + j) * K + k] * w;
    }
    float bias = b[c];
    #pragma unroll
    for (int j = 0; j < 16; ++j) {
        float v = acc[j];
        if (NORM) v *= 1.f / (float)max(g_gcnt[g0 + j], 1);
        Y[(size_t)(g0 + j) * M + c] = fmaxf(v + bias, 0.f);
    }
}

__global__ void k_final(const float* __restrict__ X, const float* __restrict__ W,
                        const float* __restrict__ b, float* __restrict__ out) {
    int g = (blockIdx.x * blockDim.x + threadIdx.x) >> 5;
    int lane = threadIdx.x & 31;
    if (g >= kG) return;
    float s = 0.f;
    #pragma unroll
    for (int k = lane; k < 256; k += 32) s += X[(size_t)g * 256 + k] * W[k];
    #pragma unroll
    for (int off = 16; off; off >>= 1) s += __shfl_down_sync(0xffffffffu, s, off);
    if (lane == 0) out[g] = s + b[0];
}

// ---------------- launch ----------------
extern "C" void kernel_launch(void* const* d_in, const int* in_sizes, int n_in,
                              void* d_out, int out_size) {
    const float* feats = (const float*)d_in[0];
    const int*   src   = (const int*)d_in[1];
    const int*   dst   = (const int*)d_in[2];
    const int*   gids  = (const int*)d_in[3];
    const float* W0 = (const float*)d_in[4];  const float* b0 = (const float*)d_in[5];
    const float* W1 = (const float*)d_in[6];  const float* b1 = (const float*)d_in[7];
    const float* W2 = (const float*)d_in[8];  const float* b2 = (const float*)d_in[9];
    const float* Wm0 = (const float*)d_in[10]; const float* bm0 = (const float*)d_in[11];
    const float* Wm1 = (const float*)d_in[12]; const float* bm1 = (const float*)d_in[13];
    const float* Wm2 = (const float*)d_in[14]; const float* bm2 = (const float*)d_in[15];
    float* out = (float*)d_out;

    float *emb, *x1, *x2;
    __half *whi, *wlo;
    cudaGetSymbolAddress((void**)&emb,  g_emb);
    cudaGetSymbolAddress((void**)&x1,   g_x1);
    cudaGetSymbolAddress((void**)&x2,   g_x2);
    cudaGetSymbolAddress((void**)&whi,  g_whi);
    cudaGetSymbolAddress((void**)&wlo,  g_wlo);

    cudaFuncSetAttribute(k_gemm_mma<0>, cudaFuncAttributeMaxDynamicSharedMemorySize,
                         kMmaSmemBytes);
    cudaFuncSetAttribute(k_gemm_mma<1>, cudaFuncAttributeMaxDynamicSharedMemorySize,
                         kMmaSmemBytes);

    const int T = 256;
    int nBlkN = (kN + T - 1) / T;           // 391
    int nBlkWarpN = (kN * 32 + T - 1) / T;  // 12500
    int nBlkTc = (kN + 127) / 128;          // 782

    k_zero_wsplit<<<kBlkZ + 192, T>>>(W0, W1, W2);
    k_degrees<<<kBlkE, T>>>(src, dst);
    k_scan1<<<kScanBlocks, 1024>>>();
    k_scan_add_inv<<<nBlkN, T>>>(gids);
    k_scatter_f2h<<<kBlkE + kBlkH, T>>>(src, dst, feats);

    k_gather<<<nBlkWarpN, T>>>();
    k_gemm_mma<0><<<nBlkTc, T, kMmaSmemBytes>>>(whi + 0 * kD * kD, wlo + 0 * kD * kD,
                                                b0, gids, kN);
    k_gather<<<nBlkWarpN, T>>>();
    k_gemm_mma<0><<<nBlkTc, T, kMmaSmemBytes>>>(whi + 1 * kD * kD, wlo + 1 * kD * kD,
                                                b1, gids, kN);
    k_gather<<<nBlkWarpN, T>>>();
    k_gemm_mma<1><<<nBlkTc, T, kMmaSmemBytes>>>(whi + 2 * kD * kD, wlo + 2 * kD * kD,
                                                b2, gids, kN);

    k_mlp<true><<<(kG / 16) * 512 / T, T>>>(emb, Wm0, bm0, x1, 128, 512);
    k_mlp<false><<<(kG / 16) * 256 / T, T>>>(x1, Wm1, bm1, x2, 512, 256);
    k_final<<<(kG * 32) / T, T>>>(x2, Wm2, bm2, out);
}

// round 16
// speedup vs baseline: 1.3686x; 1.3686x over previous
#include <cuda_runtime.h>
#include <cuda_bf16.h>
#include <cuda_fp16.h>
#include <cstdint>

constexpr int kN = 100000;
constexpr int kE = 1600000;
constexpr int kG = 2048;
constexpr int kD = 128;
constexpr int kScanBlocks = (kN + 1023) / 1024; // 98
constexpr int kBlkE = (kE + 255) / 256;          // 6250
constexpr int kBlkH = (kN * kD / 4 + 255) / 256; // 12500
constexpr int kBlkZ = (kG * kD + 255) / 256;     // 1024

// ---------------- scratch (no allocations allowed) ----------------
__device__ __half g_h16[kN * kD];            // pre-scaled rows h, fp16
__device__ __half g_m16[kN * kD];            // gathered m, fp16
__device__ __half g_whi[3 * kD * kD];        // W fp16 hi, [K][N]
__device__ __half g_wlo[3 * kD * kD];        // W fp16 lo, [K][N]
__device__ float g_inv_src[kN];
__device__ float g_inv_dst[kN];
__device__ int   g_deg_out[kN];
__device__ int   g_deg_in[kN];
__device__ int   g_row_ptr[kN + 1];
__device__ int   g_cursor[kN];
__device__ int   g_edge_src[kE];
__device__ int   g_blk[kScanBlocks];
__device__ float g_emb[kG * kD];
__device__ int   g_gcnt[kG];
__device__ float g_x1[kG * 512];
__device__ float g_x2[kG * 256];

// ---------------- mma / ldmatrix helpers (base ISA, sm_80+) ----------------
__device__ __forceinline__ uint32_t smem_u32(const void* p) {
    uint32_t a;
    asm("{ .reg .u64 t; cvta.to.shared.u64 t, %1; cvt.u32.u64 %0, t; }" : "=r"(a) : "l"(p));
    return a;
}
__device__ __forceinline__ void ldsm_x4(uint32_t* r, uint32_t addr) {
    asm volatile("ldmatrix.sync.aligned.m8n8.x4.shared.b16 {%0,%1,%2,%3}, [%4];"
                 : "=r"(r[0]), "=r"(r[1]), "=r"(r[2]), "=r"(r[3]) : "r"(addr));
}
__device__ __forceinline__ void ldsm_x4_t(uint32_t* r, uint32_t addr) {
    asm volatile("ldmatrix.sync.aligned.m8n8.x4.trans.shared.b16 {%0,%1,%2,%3}, [%4];"
                 : "=r"(r[0]), "=r"(r[1]), "=r"(r[2]), "=r"(r[3]) : "r"(addr));
}
__device__ __forceinline__ void mma16816h(float* d, const uint32_t* a, const uint32_t* b) {
    asm volatile(
        "mma.sync.aligned.m16n8k16.row.col.f32.f16.f16.f32 "
        "{%0,%1,%2,%3}, {%4,%5,%6,%7}, {%8,%9}, {%0,%1,%2,%3};"
        : "+f"(d[0]), "+f"(d[1]), "+f"(d[2]), "+f"(d[3])
        : "r"(a[0]), "r"(a[1]), "r"(a[2]), "r"(a[3]), "r"(b[0]), "r"(b[1]));
}

// ---------------- setup kernels ----------------
__global__ void k_zero_wsplit(const float* __restrict__ W0, const float* __restrict__ W1,
                              const float* __restrict__ W2) {
    if (blockIdx.x < kBlkZ) {
        int i = blockIdx.x * 256 + threadIdx.x;
        if (i < kN) { g_deg_out[i] = 0; g_deg_in[i] = 0; }
        if (i < kG * kD) g_emb[i] = 0.f;
        if (i < kG) g_gcnt[i] = 0;
    } else {
        int b = blockIdx.x - kBlkZ;
        int layer = b >> 6;
        int i = (b & 63) * 256 + threadIdx.x;
        if (i >= kD * kD) return;
        const float* W = (layer == 0) ? W0 : (layer == 1) ? W1 : W2;
        float w = W[i];
        __half h = __float2half_rn(w);
        g_whi[layer * kD * kD + i] = h;
        g_wlo[layer * kD * kD + i] = __float2half_rn(w - __half2float(h));
    }
}

__global__ void k_degrees(const int* __restrict__ src, const int* __restrict__ dst) {
    int e = blockIdx.x * blockDim.x + threadIdx.x;
    if (e >= kE) return;
    atomicAdd(&g_deg_out[src[e]], 1);
    atomicAdd(&g_deg_in[dst[e]], 1);
}

__global__ void k_scan1() {
    __shared__ int sm[1024];
    int tid = threadIdx.x;
    int i = blockIdx.x * 1024 + tid;
    int v = (i < kN) ? g_deg_in[i] : 0;
    int x = v;
    sm[tid] = x;
    __syncthreads();
    for (int off = 1; off < 1024; off <<= 1) {
        int y = (tid >= off) ? sm[tid - off] : 0;
        __syncthreads();
        x += y;
        sm[tid] = x;
        __syncthreads();
    }
    if (i < kN) g_row_ptr[i] = x - v;
    if (tid == 1023) g_blk[blockIdx.x] = x;
}

__global__ void k_scan_add_inv(const int* __restrict__ gids) {
    __shared__ int red[256];
    int tid = threadIdx.x;
    int chunk = blockIdx.x >> 2;
    int v = (tid < chunk) ? g_blk[tid] : 0;
    red[tid] = v;
    __syncthreads();
    #pragma unroll
    for (int s = 128; s; s >>= 1) {
        if (tid < s) red[tid] += red[tid + s];
        __syncthreads();
    }
    int pref = red[0];

    int i = blockIdx.x * 256 + tid;
    if (i < kN) {
        int rp = g_row_ptr[i] + pref;
        g_row_ptr[i] = rp;
        g_cursor[i]  = rp;
        g_inv_src[i] = rsqrtf((float)max(g_deg_out[i], 1));
        g_inv_dst[i] = rsqrtf((float)max(g_deg_in[i], 1));
        atomicAdd(&g_gcnt[gids[i]], 1);
    }
    if (i == 0) g_row_ptr[kN] = kE;
}

__global__ void k_scatter_f2h(const int* __restrict__ src, const int* __restrict__ dst,
                              const float* __restrict__ feats) {
    if (blockIdx.x < kBlkE) {
        int e = blockIdx.x * 256 + threadIdx.x;
        if (e >= kE) return;
        int d = dst[e];
        int pos = atomicAdd(&g_cursor[d], 1);
        g_edge_src[pos] = src[e];
    } else {
        int i = (blockIdx.x - kBlkE) * 256 + threadIdx.x;
        if (i >= kN * kD / 4) return;
        int row = i >> 5;
        float s = g_inv_src[row];
        float4 v = reinterpret_cast<const float4*>(feats)[i];
        __half2 a = __floats2half2_rn(v.x * s, v.y * s);
        __half2 b = __floats2half2_rn(v.z * s, v.w * s);
        reinterpret_cast<__half2*>(g_h16)[2 * i + 0] = a;
        reinterpret_cast<__half2*>(g_h16)[2 * i + 1] = b;
    }
}

// ---------------- GCN aggregation: one warp per dst node -> fp16 m ----------------
// R13 structure; edge ids loaded as uint4 (LDG.128) after alignment prologue.
__global__ void k_gather() {
    int w = (blockIdx.x * blockDim.x + threadIdx.x) >> 5;
    int lane = threadIdx.x & 31;
    if (w >= kN) return;
    int e0 = g_row_ptr[w];
    int e1 = g_row_ptr[w + 1];
    const uint2* H2 = reinterpret_cast<const uint2*>(g_h16);
    float4 acc = make_float4(0.f, 0.f, 0.f, 0.f);

    #define ACC(r) { \
        float2 a_ = __half22float2(*reinterpret_cast<__half2*>(&(r).x)); \
        float2 b_ = __half22float2(*reinterpret_cast<__half2*>(&(r).y)); \
        acc.x += a_.x; acc.y += a_.y; acc.z += b_.x; acc.w += b_.y; }

    int e = e0;
    // scalar prologue to 4-int (16B) alignment
    for (; e < e1 && (e & 3); ++e) {
        int s = g_edge_src[e];
        uint2 r = H2[(size_t)s * 32 + lane];
        ACC(r)
    }
    // main: two LDG.128 id loads per 8-edge block
    for (; e + 7 < e1; e += 8) {
        int4 ia = *reinterpret_cast<const int4*>(g_edge_src + e);
        int4 ib = *reinterpret_cast<const int4*>(g_edge_src + e + 4);
        uint2 r0 = H2[(size_t)ia.x * 32 + lane];
        uint2 r1 = H2[(size_t)ia.y * 32 + lane];
        uint2 r2 = H2[(size_t)ia.z * 32 + lane];
        uint2 r3 = H2[(size_t)ia.w * 32 + lane];
        uint2 r4 = H2[(size_t)ib.x * 32 + lane];
        uint2 r5 = H2[(size_t)ib.y * 32 + lane];
        uint2 r6 = H2[(size_t)ib.z * 32 + lane];
        uint2 r7 = H2[(size_t)ib.w * 32 + lane];
        ACC(r0) ACC(r1) ACC(r2) ACC(r3) ACC(r4) ACC(r5) ACC(r6) ACC(r7)
    }
    // drain
    for (; e < e1; ++e) {
        int s = g_edge_src[e];
        uint2 r = H2[(size_t)s * 32 + lane];
        ACC(r)
    }
    #undef ACC

    float wd = g_inv_dst[w];
    uint2 o;
    *reinterpret_cast<__half2*>(&o.x) = __floats2half2_rn(acc.x * wd, acc.y * wd);
    *reinterpret_cast<__half2*>(&o.y) = __floats2half2_rn(acc.z * wd, acc.w * wd);
    reinterpret_cast<uint2*>(g_m16)[(size_t)w * 32 + lane] = o;
}

// ---------------- mma.sync GEMM: [128,128] tile, fp16 A x (fp16 hi+lo W), fp32 acc ----------------
constexpr int kSA = 136;
constexpr int kTileB = 128 * kSA * 2;            // 34816 bytes
constexpr int kOffA   = 0;
constexpr int kOffBhi = kTileB;
constexpr int kOffBlo = 2 * kTileB;
constexpr int kMmaSmemBytes = 3 * kTileB;        // 104448 -> 2 CTAs/SM

__device__ __forceinline__ void stage_tile(char* smem, int off,
                                           const unsigned short* __restrict__ src,
                                           int row0, int rows, int tid) {
    #pragma unroll
    for (int it = 0; it < 8; ++it) {
        int chunk = tid + it * 256;
        int r = chunk >> 4;
        int c8 = (chunk & 15) << 3;
        uint4 v = make_uint4(0u, 0u, 0u, 0u);
        int gr = row0 + r;
        if (gr < rows) v = *reinterpret_cast<const uint4*>(src + (size_t)gr * 128 + c8);
        *reinterpret_cast<uint4*>(smem + off + (r * kSA + c8) * 2) = v;
    }
}

// EPI=0: write fp16 h PRE-SCALED by inv_src[row]; EPI=1: atomicAdd into g_emb
template <int EPI>
__global__ void __launch_bounds__(256, 2)
k_gemm_mma(const __half* __restrict__ Bhi, const __half* __restrict__ Blo,
           const float* __restrict__ bias, const int* __restrict__ gids, int rows) {
    extern __shared__ char smem[];
    uint32_t sb = smem_u32(smem);
    int tid = threadIdx.x;
    int lane = tid & 31;
    int wid = tid >> 5;
    int row0 = blockIdx.x * 128;

    stage_tile(smem, kOffA, reinterpret_cast<const unsigned short*>(g_m16), row0, rows, tid);
    stage_tile(smem, kOffBhi, reinterpret_cast<const unsigned short*>(Bhi), 0, 128, tid);
    stage_tile(smem, kOffBlo, reinterpret_cast<const unsigned short*>(Blo), 0, 128, tid);
    __syncthreads();

    int wm = wid & 3;
    int wn = wid >> 2;
    int base_m = wm * 32;
    int base_n = wn * 64;

    int l16 = lane & 15;
    int c8  = (lane >> 4) << 3;
    uint32_t a_base = sb + ((base_m + l16) * kSA + c8) * 2;
    uint32_t b_base = sb + (l16 * kSA + base_n + c8) * 2;

    float acc[16][4];
    #pragma unroll
    for (int t = 0; t < 16; ++t)
        #pragma unroll
        for (int j = 0; j < 4; ++j) acc[t][j] = 0.f;

    #pragma unroll
    for (int pass = 0; pass < 2; ++pass) {
        int offB = (pass == 0) ? kOffBhi : kOffBlo;
        #pragma unroll
        for (int ks = 0; ks < 8; ++ks) {
            uint32_t af[2][4];
            ldsm_x4(af[0], a_base + kOffA + 0 * 16 * kSA * 2 + ks * 32);
            ldsm_x4(af[1], a_base + kOffA + 1 * 16 * kSA * 2 + ks * 32);
            uint32_t bf[4][4];
            #pragma unroll
            for (int np = 0; np < 4; ++np)
                ldsm_x4_t(bf[np], b_base + offB + ks * 16 * kSA * 2 + np * 32);
            #pragma unroll
            for (int mt = 0; mt < 2; ++mt)
                #pragma unroll
                for (int nt = 0; nt < 8; ++nt)
                    mma16816h(acc[mt * 8 + nt], af[mt], &bf[nt >> 1][(nt & 1) * 2]);
        }
    }

    #pragma unroll
    for (int mt = 0; mt < 2; ++mt) {
        int r0 = row0 + base_m + mt * 16 + (lane >> 2);
        int r1 = r0 + 8;
        int gid0 = -1, gid1 = -1;
        float sc0 = 0.f, sc1 = 0.f;
        if (EPI == 1) {
            if (r0 < rows) gid0 = gids[r0];
            if (r1 < rows) gid1 = gids[r1];
        } else {
            if (r0 < rows) sc0 = g_inv_src[r0];
            if (r1 < rows) sc1 = g_inv_src[r1];
        }
        #pragma unroll
        for (int nt = 0; nt < 8; ++nt) {
            const float* a = acc[mt * 8 + nt];
            int col = base_n + nt * 8 + ((lane & 3) << 1);
            float2 bb = *reinterpret_cast<const float2*>(&bias[col]);
            float o0x = fmaxf(a[0] + bb.x, 0.f);
            float o0y = fmaxf(a[1] + bb.y, 0.f);
            float o1x = fmaxf(a[2] + bb.x, 0.f);
            float o1y = fmaxf(a[3] + bb.y, 0.f);
            if (EPI == 0) {
                if (r0 < rows)
                    *reinterpret_cast<__half2*>(g_h16 + (size_t)r0 * 128 + col) =
                        __floats2half2_rn(o0x * sc0, o0y * sc0);
                if (r1 < rows)
                    *reinterpret_cast<__half2*>(g_h16 + (size_t)r1 * 128 + col) =
                        __floats2half2_rn(o1x * sc1, o1y * sc1);
            } else {
                if (gid0 >= 0) {
                    atomicAdd(g_emb + (size_t)gid0 * 128 + col,     o0x);
                    atomicAdd(g_emb + (size_t)gid0 * 128 + col + 1, o0y);
                }
                if (gid1 >= 0) {
                    atomicAdd(g_emb + (size_t)gid1 * 128 + col,     o1x);
                    atomicAdd(g_emb + (size_t)gid1 * 128 + col + 1, o1y);
                }
            }
        }
    }
}

// ---------------- MLP head (R13 version: 8 graphs per thread) ----------------
template <bool NORM>
__global__ void k_mlp(const float* __restrict__ X, const float* __restrict__ W,
                      const float* __restrict__ b, float* __restrict__ Y,
                      int K, int M) {
    int idx = blockIdx.x * blockDim.x + threadIdx.x;
    int c = idx % M;
    int g0 = (idx / M) * 8;
    if (g0 >= kG) return;
    float acc[8];
    #pragma unroll
    for (int j = 0; j < 8; ++j) acc[j] = 0.f;
    for (int k = 0; k < K; ++k) {
        float w = W[(size_t)k * M + c];
        #pragma unroll
        for (int j = 0; j < 8; ++j)
            acc[j] += X[(size_t)(g0 + j) * K + k] * w;
    }
    float bias = b[c];
    #pragma unroll
    for (int j = 0; j < 8; ++j) {
        float v = acc[j];
        if (NORM) v *= 1.f / (float)max(g_gcnt[g0 + j], 1);
        Y[(size_t)(g0 + j) * M + c] = fmaxf(v + bias, 0.f);
    }
}

__global__ void k_final(const float* __restrict__ X, const float* __restrict__ W,
                        const float* __restrict__ b, float* __restrict__ out) {
    int g = (blockIdx.x * blockDim.x + threadIdx.x) >> 5;
    int lane = threadIdx.x & 31;
    if (g >= kG) return;
    float s = 0.f;
    #pragma unroll
    for (int k = lane; k < 256; k += 32) s += X[(size_t)g * 256 + k] * W[k];
    #pragma unroll
    for (int off = 16; off; off >>= 1) s += __shfl_down_sync(0xffffffffu, s, off);
    if (lane == 0) out[g] = s + b[0];
}

// ---------------- launch ----------------
extern "C" void kernel_launch(void* const* d_in, const int* in_sizes, int n_in,
                              void* d_out, int out_size) {
    const float* feats = (const float*)d_in[0];
    const int*   src   = (const int*)d_in[1];
    const int*   dst   = (const int*)d_in[2];
    const int*   gids  = (const int*)d_in[3];
    const float* W0 = (const float*)d_in[4];  const float* b0 = (const float*)d_in[5];
    const float* W1 = (const float*)d_in[6];  const float* b1 = (const float*)d_in[7];
    const float* W2 = (const float*)d_in[8];  const float* b2 = (const float*)d_in[9];
    const float* Wm0 = (const float*)d_in[10]; const float* bm0 = (const float*)d_in[11];
    const float* Wm1 = (const float*)d_in[12]; const float* bm1 = (const float*)d_in[13];
    const float* Wm2 = (const float*)d_in[14]; const float* bm2 = (const float*)d_in[15];
    float* out = (float*)d_out;

    float *emb, *x1, *x2;
    __half *whi, *wlo;
    cudaGetSymbolAddress((void**)&emb,  g_emb);
    cudaGetSymbolAddress((void**)&x1,   g_x1);
    cudaGetSymbolAddress((void**)&x2,   g_x2);
    cudaGetSymbolAddress((void**)&whi,  g_whi);
    cudaGetSymbolAddress((void**)&wlo,  g_wlo);

    cudaFuncSetAttribute(k_gemm_mma<0>, cudaFuncAttributeMaxDynamicSharedMemorySize,
                         kMmaSmemBytes);
    cudaFuncSetAttribute(k_gemm_mma<1>, cudaFuncAttributeMaxDynamicSharedMemorySize,
                         kMmaSmemBytes);

    const int T = 256;
    int nBlkN = (kN + T - 1) / T;           // 391
    int nBlkWarpN = (kN * 32 + T - 1) / T;  // 12500
    int nBlkTc = (kN + 127) / 128;          // 782

    k_zero_wsplit<<<kBlkZ + 192, T>>>(W0, W1, W2);
    k_degrees<<<kBlkE, T>>>(src, dst);
    k_scan1<<<kScanBlocks, 1024>>>();
    k_scan_add_inv<<<nBlkN, T>>>(gids);
    k_scatter_f2h<<<kBlkE + kBlkH, T>>>(src, dst, feats);

    k_gather<<<nBlkWarpN, T>>>();
    k_gemm_mma<0><<<nBlkTc, T, kMmaSmemBytes>>>(whi + 0 * kD * kD, wlo + 0 * kD * kD,
                                                b0, gids, kN);
    k_gather<<<nBlkWarpN, T>>>();
    k_gemm_mma<0><<<nBlkTc, T, kMmaSmemBytes>>>(whi + 1 * kD * kD, wlo + 1 * kD * kD,
                                                b1, gids, kN);
    k_gather<<<nBlkWarpN, T>>>();
    k_gemm_mma<1><<<nBlkTc, T, kMmaSmemBytes>>>(whi + 2 * kD * kD, wlo + 2 * kD * kD,
                                                b2, gids, kN);

    k_mlp<true><<<(kG / 8) * 512 / T, T>>>(emb, Wm0, bm0, x1, 128, 512);
    k_mlp<false><<<(kG / 8) * 256 / T, T>>>(x1, Wm1, bm1, x2, 512, 256);
    k_final<<<(kG * 32) / T, T>>>(x2, Wm2, bm2, out);
}

// round 17
// speedup vs baseline: 1.3946x; 1.0191x over previous
#include <cuda_runtime.h>
#include <cuda_bf16.h>
#include <cuda_fp16.h>
#include <cstdint>

constexpr int kN = 100000;
constexpr int kE = 1600000;
constexpr int kG = 2048;
constexpr int kD = 128;
constexpr int kScanBlocks = (kN + 1023) / 1024; // 98
constexpr int kBlkE4 = (kE / 4 + 255) / 256;     // 1563 (4 edges per thread)
constexpr int kBlkH = (kN * kD / 4 + 255) / 256; // 12500
constexpr int kBlkZ = (kG * kD + 255) / 256;     // 1024

// ---------------- scratch (no allocations allowed) ----------------
__device__ __half g_h16[kN * kD];            // pre-scaled rows h, fp16
__device__ __half g_m16[kN * kD];            // gathered m, fp16
__device__ __half g_whi[3 * kD * kD];        // W fp16 hi, [K][N]
__device__ __half g_wlo[3 * kD * kD];        // W fp16 lo, [K][N]
__device__ float g_inv_src[kN];
__device__ float g_inv_dst[kN];
__device__ int   g_deg_out[kN];
__device__ int   g_deg_in[kN];
__device__ int   g_row_ptr[kN + 1];
__device__ int   g_cursor[kN];
__device__ int   g_edge_src[kE];
__device__ int   g_blk[kScanBlocks];
__device__ float g_emb[kG * kD];
__device__ int   g_gcnt[kG];
__device__ float g_x1[kG * 512];
__device__ float g_x2[kG * 256];

// ---------------- mma / ldmatrix helpers (base ISA, sm_80+) ----------------
__device__ __forceinline__ uint32_t smem_u32(const void* p) {
    uint32_t a;
    asm("{ .reg .u64 t; cvta.to.shared.u64 t, %1; cvt.u32.u64 %0, t; }" : "=r"(a) : "l"(p));
    return a;
}
__device__ __forceinline__ void ldsm_x4(uint32_t* r, uint32_t addr) {
    asm volatile("ldmatrix.sync.aligned.m8n8.x4.shared.b16 {%0,%1,%2,%3}, [%4];"
                 : "=r"(r[0]), "=r"(r[1]), "=r"(r[2]), "=r"(r[3]) : "r"(addr));
}
__device__ __forceinline__ void ldsm_x4_t(uint32_t* r, uint32_t addr) {
    asm volatile("ldmatrix.sync.aligned.m8n8.x4.trans.shared.b16 {%0,%1,%2,%3}, [%4];"
                 : "=r"(r[0]), "=r"(r[1]), "=r"(r[2]), "=r"(r[3]) : "r"(addr));
}
__device__ __forceinline__ void mma16816h(float* d, const uint32_t* a, const uint32_t* b) {
    asm volatile(
        "mma.sync.aligned.m16n8k16.row.col.f32.f16.f16.f32 "
        "{%0,%1,%2,%3}, {%4,%5,%6,%7}, {%8,%9}, {%0,%1,%2,%3};"
        : "+f"(d[0]), "+f"(d[1]), "+f"(d[2]), "+f"(d[3])
        : "r"(a[0]), "r"(a[1]), "r"(a[2]), "r"(a[3]), "r"(b[0]), "r"(b[1]));
}

// ---------------- setup kernels ----------------
__global__ void k_zero_wsplit(const float* __restrict__ W0, const float* __restrict__ W1,
                              const float* __restrict__ W2) {
    if (blockIdx.x < kBlkZ) {
        int i = blockIdx.x * 256 + threadIdx.x;
        if (i < kN) { g_deg_out[i] = 0; g_deg_in[i] = 0; }
        if (i < kG * kD) g_emb[i] = 0.f;
        if (i < kG) g_gcnt[i] = 0;
    } else {
        int b = blockIdx.x - kBlkZ;
        int layer = b >> 6;
        int i = (b & 63) * 256 + threadIdx.x;
        if (i >= kD * kD) return;
        const float* W = (layer == 0) ? W0 : (layer == 1) ? W1 : W2;
        float w = W[i];
        __half h = __float2half_rn(w);
        g_whi[layer * kD * kD + i] = h;
        g_wlo[layer * kD * kD + i] = __float2half_rn(w - __half2float(h));
    }
}

// degrees: 4 edges per thread, int4 loads (kE divisible by 4)
__global__ void k_degrees(const int* __restrict__ src, const int* __restrict__ dst) {
    int t = blockIdx.x * blockDim.x + threadIdx.x;
    if (t >= kE / 4) return;
    int4 s4 = reinterpret_cast<const int4*>(src)[t];
    int4 d4 = reinterpret_cast<const int4*>(dst)[t];
    atomicAdd(&g_deg_out[s4.x], 1);
    atomicAdd(&g_deg_out[s4.y], 1);
    atomicAdd(&g_deg_out[s4.z], 1);
    atomicAdd(&g_deg_out[s4.w], 1);
    atomicAdd(&g_deg_in[d4.x], 1);
    atomicAdd(&g_deg_in[d4.y], 1);
    atomicAdd(&g_deg_in[d4.z], 1);
    atomicAdd(&g_deg_in[d4.w], 1);
}

__global__ void k_scan1() {
    __shared__ int sm[1024];
    int tid = threadIdx.x;
    int i = blockIdx.x * 1024 + tid;
    int v = (i < kN) ? g_deg_in[i] : 0;
    int x = v;
    sm[tid] = x;
    __syncthreads();
    for (int off = 1; off < 1024; off <<= 1) {
        int y = (tid >= off) ? sm[tid - off] : 0;
        __syncthreads();
        x += y;
        sm[tid] = x;
        __syncthreads();
    }
    if (i < kN) g_row_ptr[i] = x - v;
    if (tid == 1023) g_blk[blockIdx.x] = x;
}

__global__ void k_scan_add_inv(const int* __restrict__ gids) {
    __shared__ int red[256];
    int tid = threadIdx.x;
    int chunk = blockIdx.x >> 2;
    int v = (tid < chunk) ? g_blk[tid] : 0;
    red[tid] = v;
    __syncthreads();
    #pragma unroll
    for (int s = 128; s; s >>= 1) {
        if (tid < s) red[tid] += red[tid + s];
        __syncthreads();
    }
    int pref = red[0];

    int i = blockIdx.x * 256 + tid;
    if (i < kN) {
        int rp = g_row_ptr[i] + pref;
        g_row_ptr[i] = rp;
        g_cursor[i]  = rp;
        g_inv_src[i] = rsqrtf((float)max(g_deg_out[i], 1));
        g_inv_dst[i] = rsqrtf((float)max(g_deg_in[i], 1));
        atomicAdd(&g_gcnt[gids[i]], 1);
    }
    if (i == 0) g_row_ptr[kN] = kE;
}

// scatter (4 edges/thread, int4 loads) + fused feats fp32 -> fp16 pre-scaled
__global__ void k_scatter_f2h(const int* __restrict__ src, const int* __restrict__ dst,
                              const float* __restrict__ feats) {
    if (blockIdx.x < kBlkE4) {
        int t = blockIdx.x * 256 + threadIdx.x;
        if (t >= kE / 4) return;
        int4 s4 = reinterpret_cast<const int4*>(src)[t];
        int4 d4 = reinterpret_cast<const int4*>(dst)[t];
        g_edge_src[atomicAdd(&g_cursor[d4.x], 1)] = s4.x;
        g_edge_src[atomicAdd(&g_cursor[d4.y], 1)] = s4.y;
        g_edge_src[atomicAdd(&g_cursor[d4.z], 1)] = s4.z;
        g_edge_src[atomicAdd(&g_cursor[d4.w], 1)] = s4.w;
    } else {
        int i = (blockIdx.x - kBlkE4) * 256 + threadIdx.x;
        if (i >= kN * kD / 4) return;
        int row = i >> 5;
        float s = g_inv_src[row];
        float4 v = reinterpret_cast<const float4*>(feats)[i];
        __half2 a = __floats2half2_rn(v.x * s, v.y * s);
        __half2 b = __floats2half2_rn(v.z * s, v.w * s);
        reinterpret_cast<__half2*>(g_h16)[2 * i + 0] = a;
        reinterpret_cast<__half2*>(g_h16)[2 * i + 1] = b;
    }
}

// ---------------- GCN aggregation: one warp per dst node -> fp16 m (R13 exact) ----------------
__global__ void k_gather() {
    int w = (blockIdx.x * blockDim.x + threadIdx.x) >> 5;
    int lane = threadIdx.x & 31;
    if (w >= kN) return;
    int e0 = g_row_ptr[w];
    int e1 = g_row_ptr[w + 1];
    const uint2* H2 = reinterpret_cast<const uint2*>(g_h16);
    float4 acc = make_float4(0.f, 0.f, 0.f, 0.f);
    int e = e0;
    for (; e + 7 < e1; e += 8) {
        int s0 = g_edge_src[e + 0];
        int s1 = g_edge_src[e + 1];
        int s2 = g_edge_src[e + 2];
        int s3 = g_edge_src[e + 3];
        int s4 = g_edge_src[e + 4];
        int s5 = g_edge_src[e + 5];
        int s6 = g_edge_src[e + 6];
        int s7 = g_edge_src[e + 7];
        uint2 r0 = H2[(size_t)s0 * 32 + lane];
        uint2 r1 = H2[(size_t)s1 * 32 + lane];
        uint2 r2 = H2[(size_t)s2 * 32 + lane];
        uint2 r3 = H2[(size_t)s3 * 32 + lane];
        uint2 r4 = H2[(size_t)s4 * 32 + lane];
        uint2 r5 = H2[(size_t)s5 * 32 + lane];
        uint2 r6 = H2[(size_t)s6 * 32 + lane];
        uint2 r7 = H2[(size_t)s7 * 32 + lane];
        #define ACC(r) { \
            float2 a_ = __half22float2(*reinterpret_cast<__half2*>(&(r).x)); \
            float2 b_ = __half22float2(*reinterpret_cast<__half2*>(&(r).y)); \
            acc.x += a_.x; acc.y += a_.y; acc.z += b_.x; acc.w += b_.y; }
        ACC(r0) ACC(r1) ACC(r2) ACC(r3) ACC(r4) ACC(r5) ACC(r6) ACC(r7)
    }
    for (; e < e1; ++e) {
        int s = g_edge_src[e];
        uint2 r = H2[(size_t)s * 32 + lane];
        ACC(r)
    }
    #undef ACC
    float wd = g_inv_dst[w];
    uint2 o;
    *reinterpret_cast<__half2*>(&o.x) = __floats2half2_rn(acc.x * wd, acc.y * wd);
    *reinterpret_cast<__half2*>(&o.y) = __floats2half2_rn(acc.z * wd, acc.w * wd);
    reinterpret_cast<uint2*>(g_m16)[(size_t)w * 32 + lane] = o;
}

// ---------------- mma.sync GEMM: [128,128] tile, fp16 A x (fp16 hi+lo W), fp32 acc ----------------
constexpr int kSA = 136;
constexpr int kTileB = 128 * kSA * 2;            // 34816 bytes
constexpr int kOffA   = 0;
constexpr int kOffBhi = kTileB;
constexpr int kOffBlo = 2 * kTileB;
constexpr int kMmaSmemBytes = 3 * kTileB;        // 104448 -> 2 CTAs/SM

__device__ __forceinline__ void stage_tile(char* smem, int off,
                                           const unsigned short* __restrict__ src,
                                           int row0, int rows, int tid) {
    #pragma unroll
    for (int it = 0; it < 8; ++it) {
        int chunk = tid + it * 256;
        int r = chunk >> 4;
        int c8 = (chunk & 15) << 3;
        uint4 v = make_uint4(0u, 0u, 0u, 0u);
        int gr = row0 + r;
        if (gr < rows) v = *reinterpret_cast<const uint4*>(src + (size_t)gr * 128 + c8);
        *reinterpret_cast<uint4*>(smem + off + (r * kSA + c8) * 2) = v;
    }
}

// EPI=0: write fp16 h PRE-SCALED by inv_src[row]; EPI=1: atomicAdd into g_emb
template <int EPI>
__global__ void __launch_bounds__(256, 2)
k_gemm_mma(const __half* __restrict__ Bhi, const __half* __restrict__ Blo,
           const float* __restrict__ bias, const int* __restrict__ gids, int rows) {
    extern __shared__ char smem[];
    uint32_t sb = smem_u32(smem);
    int tid = threadIdx.x;
    int lane = tid & 31;
    int wid = tid >> 5;
    int row0 = blockIdx.x * 128;

    stage_tile(smem, kOffA, reinterpret_cast<const unsigned short*>(g_m16), row0, rows, tid);
    stage_tile(smem, kOffBhi, reinterpret_cast<const unsigned short*>(Bhi), 0, 128, tid);
    stage_tile(smem, kOffBlo, reinterpret_cast<const unsigned short*>(Blo), 0, 128, tid);
    __syncthreads();

    int wm = wid & 3;
    int wn = wid >> 2;
    int base_m = wm * 32;
    int base_n = wn * 64;

    int l16 = lane & 15;
    int c8  = (lane >> 4) << 3;
    uint32_t a_base = sb + ((base_m + l16) * kSA + c8) * 2;
    uint32_t b_base = sb + (l16 * kSA + base_n + c8) * 2;

    float acc[16][4];
    #pragma unroll
    for (int t = 0; t < 16; ++t)
        #pragma unroll
        for (int j = 0; j < 4; ++j) acc[t][j] = 0.f;

    #pragma unroll
    for (int pass = 0; pass < 2; ++pass) {
        int offB = (pass == 0) ? kOffBhi : kOffBlo;
        #pragma unroll
        for (int ks = 0; ks < 8; ++ks) {
            uint32_t af[2][4];
            ldsm_x4(af[0], a_base + kOffA + 0 * 16 * kSA * 2 + ks * 32);
            ldsm_x4(af[1], a_base + kOffA + 1 * 16 * kSA * 2 + ks * 32);
            uint32_t bf[4][4];
            #pragma unroll
            for (int np = 0; np < 4; ++np)
                ldsm_x4_t(bf[np], b_base + offB + ks * 16 * kSA * 2 + np * 32);
            #pragma unroll
            for (int mt = 0; mt < 2; ++mt)
                #pragma unroll
                for (int nt = 0; nt < 8; ++nt)
                    mma16816h(acc[mt * 8 + nt], af[mt], &bf[nt >> 1][(nt & 1) * 2]);
        }
    }

    #pragma unroll
    for (int mt = 0; mt < 2; ++mt) {
        int r0 = row0 + base_m + mt * 16 + (lane >> 2);
        int r1 = r0 + 8;
        int gid0 = -1, gid1 = -1;
        float sc0 = 0.f, sc1 = 0.f;
        if (EPI == 1) {
            if (r0 < rows) gid0 = gids[r0];
            if (r1 < rows) gid1 = gids[r1];
        } else {
            if (r0 < rows) sc0 = g_inv_src[r0];
            if (r1 < rows) sc1 = g_inv_src[r1];
        }
        #pragma unroll
        for (int nt = 0; nt < 8; ++nt) {
            const float* a = acc[mt * 8 + nt];
            int col = base_n + nt * 8 + ((lane & 3) << 1);
            float2 bb = *reinterpret_cast<const float2*>(&bias[col]);
            float o0x = fmaxf(a[0] + bb.x, 0.f);
            float o0y = fmaxf(a[1] + bb.y, 0.f);
            float o1x = fmaxf(a[2] + bb.x, 0.f);
            float o1y = fmaxf(a[3] + bb.y, 0.f);
            if (EPI == 0) {
                if (r0 < rows)
                    *reinterpret_cast<__half2*>(g_h16 + (size_t)r0 * 128 + col) =
                        __floats2half2_rn(o0x * sc0, o0y * sc0);
                if (r1 < rows)
                    *reinterpret_cast<__half2*>(g_h16 + (size_t)r1 * 128 + col) =
                        __floats2half2_rn(o1x * sc1, o1y * sc1);
            } else {
                if (gid0 >= 0) {
                    atomicAdd(g_emb + (size_t)gid0 * 128 + col,     o0x);
                    atomicAdd(g_emb + (size_t)gid0 * 128 + col + 1, o0y);
                }
                if (gid1 >= 0) {
                    atomicAdd(g_emb + (size_t)gid1 * 128 + col,     o1x);
                    atomicAdd(g_emb + (size_t)gid1 * 128 + col + 1, o1y);
                }
            }
        }
    }
}

// ---------------- MLP head (R13 version: 8 graphs per thread) ----------------
template <bool NORM>
__global__ void k_mlp(const float* __restrict__ X, const float* __restrict__ W,
                      const float* __restrict__ b, float* __restrict__ Y,
                      int K, int M) {
    int idx = blockIdx.x * blockDim.x + threadIdx.x;
    int c = idx % M;
    int g0 = (idx / M) * 8;
    if (g0 >= kG) return;
    float acc[8];
    #pragma unroll
    for (int j = 0; j < 8; ++j) acc[j] = 0.f;
    for (int k = 0; k < K; ++k) {
        float w = W[(size_t)k * M + c];
        #pragma unroll
        for (int j = 0; j < 8; ++j)
            acc[j] += X[(size_t)(g0 + j) * K + k] * w;
    }
    float bias = b[c];
    #pragma unroll
    for (int j = 0; j < 8; ++j) {
        float v = acc[j];
        if (NORM) v *= 1.f / (float)max(g_gcnt[g0 + j], 1);
        Y[(size_t)(g0 + j) * M + c] = fmaxf(v + bias, 0.f);
    }
}

__global__ void k_final(const float* __restrict__ X, const float* __restrict__ W,
                        const float* __restrict__ b, float* __restrict__ out) {
    int g = (blockIdx.x * blockDim.x + threadIdx.x) >> 5;
    int lane = threadIdx.x & 31;
    if (g >= kG) return;
    float s = 0.f;
    #pragma unroll
    for (int k = lane; k < 256; k += 32) s += X[(size_t)g * 256 + k] * W[k];
    #pragma unroll
    for (int off = 16; off; off >>= 1) s += __shfl_down_sync(0xffffffffu, s, off);
    if (lane == 0) out[g] = s + b[0];
}

// ---------------- launch ----------------
extern "C" void kernel_launch(void* const* d_in, const int* in_sizes, int n_in,
                              void* d_out, int out_size) {
    const float* feats = (const float*)d_in[0];
    const int*   src   = (const int*)d_in[1];
    const int*   dst   = (const int*)d_in[2];
    const int*   gids  = (const int*)d_in[3];
    const float* W0 = (const float*)d_in[4];  const float* b0 = (const float*)d_in[5];
    const float* W1 = (const float*)d_in[6];  const float* b1 = (const float*)d_in[7];
    const float* W2 = (const float*)d_in[8];  const float* b2 = (const float*)d_in[9];
    const float* Wm0 = (const float*)d_in[10]; const float* bm0 = (const float*)d_in[11];
    const float* Wm1 = (const float*)d_in[12]; const float* bm1 = (const float*)d_in[13];
    const float* Wm2 = (const float*)d_in[14]; const float* bm2 = (const float*)d_in[15];
    float* out = (float*)d_out;

    float *emb, *x1, *x2;
    __half *whi, *wlo;
    cudaGetSymbolAddress((void**)&emb,  g_emb);
    cudaGetSymbolAddress((void**)&x1,   g_x1);
    cudaGetSymbolAddress((void**)&x2,   g_x2);
    cudaGetSymbolAddress((void**)&whi,  g_whi);
    cudaGetSymbolAddress((void**)&wlo,  g_wlo);

    cudaFuncSetAttribute(k_gemm_mma<0>, cudaFuncAttributeMaxDynamicSharedMemorySize,
                         kMmaSmemBytes);
    cudaFuncSetAttribute(k_gemm_mma<1>, cudaFuncAttributeMaxDynamicSharedMemorySize,
                         kMmaSmemBytes);

    const int T = 256;
    int nBlkN = (kN + T - 1) / T;           // 391
    int nBlkWarpN = (kN * 32 + T - 1) / T;  // 12500
    int nBlkTc = (kN + 127) / 128;          // 782

    k_zero_wsplit<<<kBlkZ + 192, T>>>(W0, W1, W2);
    k_degrees<<<kBlkE4, T>>>(src, dst);
    k_scan1<<<kScanBlocks, 1024>>>();
    k_scan_add_inv<<<nBlkN, T>>>(gids);
    k_scatter_f2h<<<kBlkE4 + kBlkH, T>>>(src, dst, feats);

    k_gather<<<nBlkWarpN, T>>>();
    k_gemm_mma<0><<<nBlkTc, T, kMmaSmemBytes>>>(whi + 0 * kD * kD, wlo + 0 * kD * kD,
                                                b0, gids, kN);
    k_gather<<<nBlkWarpN, T>>>();
    k_gemm_mma<0><<<nBlkTc, T, kMmaSmemBytes>>>(whi + 1 * kD * kD, wlo + 1 * kD * kD,
                                                b1, gids, kN);
    k_gather<<<nBlkWarpN, T>>>();
    k_gemm_mma<1><<<nBlkTc, T, kMmaSmemBytes>>>(whi + 2 * kD * kD, wlo + 2 * kD * kD,
                                                b2, gids, kN);

    k_mlp<true><<<(kG / 8) * 512 / T, T>>>(emb, Wm0, bm0, x1, 128, 512);
    k_mlp<false><<<(kG / 8) * 256 / T, T>>>(x1, Wm1, bm1, x2, 512, 256);
    k_final<<<(kG * 32) / T, T>>>(x2, Wm2, bm2, out);
}